// round 16
// baseline (speedup 1.0000x reference)
#include <cuda_runtime.h>

#define TT 2048
#define DD 1024
#define HH 16

// ---------------- scratch (static device globals; no allocations) -------------
__device__ float g_qkv[TT * 3 * DD];     // [t][3*1024]  (q|k|v per token)
__device__ float g_kvgeo[TT * 2 * DD];   // [t][2*1024]  (k_geo|v_geo)
__device__ float g_proj[4 * TT * 64];    // P1|P2|R1|R2, each [t][64]
__device__ float g_jw[HH * 6 * TT];      // [h][c][t]    J6-applied write lines
__device__ float g_read[TT * HH * 6];    // [t][h][c]    read lines
__device__ float g_gate[HH * TT];        // [h][t]       gram gate
__device__ float g_attno[TT * DD];       // [t][h*64+d]  attention output (tf32-rounded)
// tf32-pre-rounded operand copies for the cp.async GEMMs
__device__ float g_xr[TT * DD];          // rounded x
__device__ float g_qwr[DD * 3 * DD];     // rounded qkv_w
__device__ float g_gwr[DD * 2 * DD];     // rounded kv_geo_w
__device__ float g_owr[DD * DD];         // rounded out_w

// ---------------- tf32 helpers ----------------------------------------------
__device__ __forceinline__ unsigned f2tf(float f) {
    unsigned r;
    asm("cvt.rna.tf32.f32 %0, %1;" : "=r"(r) : "f"(f));
    return r;
}

__device__ __forceinline__ void mma_tf32(float* c, const unsigned* a, const unsigned* b) {
    asm volatile(
        "mma.sync.aligned.m16n8k8.row.col.f32.tf32.tf32.f32 "
        "{%0,%1,%2,%3}, {%4,%5,%6,%7}, {%8,%9}, {%0,%1,%2,%3};"
        : "+f"(c[0]), "+f"(c[1]), "+f"(c[2]), "+f"(c[3])
        : "r"(a[0]), "r"(a[1]), "r"(a[2]), "r"(a[3]), "r"(b[0]), "r"(b[1]));
}

__device__ __forceinline__ void cp_async16(void* smem_dst, const void* gmem_src) {
    unsigned dst = (unsigned)__cvta_generic_to_shared(smem_dst);
    asm volatile("cp.async.ca.shared.global [%0], [%1], 16;"
                 :: "r"(dst), "l"(gmem_src));
}
__device__ __forceinline__ void cp_async_commit() {
    asm volatile("cp.async.commit_group;" ::: "memory");
}
__device__ __forceinline__ void cp_async_wait0() {
    asm volatile("cp.async.wait_group 0;" ::: "memory");
}

// ---------------- tf32 pre-rounding (RNA), float4 vectorized -----------------
__global__ __launch_bounds__(256) void round_tf32(
    const float4* __restrict__ src, float4* __restrict__ dst)
{
    const int i = blockIdx.x * 256 + threadIdx.x;
    float4 v = src[i];
    float4 o;
    o.x = __uint_as_float(f2tf(v.x));
    o.y = __uint_as_float(f2tf(v.y));
    o.z = __uint_as_float(f2tf(v.z));
    o.w = __uint_as_float(f2tf(v.w));
    dst[i] = o;
}

// ========== big tf32 GEMM: cp.async double buffer, pre-rounded inputs ========
#define A_ST 36
#define B_ST 72
#define A_WORDS (128 * A_ST)     // 4608
#define B_WORDS (32 * B_ST)      // 2304
#define GEMM_SMEM_BYTES (2 * (A_WORDS + B_WORDS) * 4)   // 55296

__global__ __launch_bounds__(256) void gemm_tf32(
    const float* __restrict__ A, const float* __restrict__ B,
    const float* __restrict__ bias, float* __restrict__ C,
    int M, int N, int K)
{
    extern __shared__ unsigned sm[];
    unsigned* const As0 = sm;
    unsigned* const As1 = sm + A_WORDS;
    unsigned* const Bs0 = sm + 2 * A_WORDS;
    unsigned* const Bs1 = sm + 2 * A_WORDS + B_WORDS;

    const int tid = threadIdx.x;
    const int lane = tid & 31, warp = tid >> 5;
    const int wm = (warp & 3) << 5;
    const int wn = (warp >> 2) << 5;
    const int m0 = blockIdx.y << 7, n0 = blockIdx.x << 6;
    const int lr = lane >> 2, lc = lane & 3;

    const int am = tid >> 3, ak = (tid & 7) << 2;
    const int bk = tid >> 4, bn = (tid & 15) << 2;

    const float* Aptr = A + (size_t)(m0 + am) * K + ak;
    const float* Bptr = B + (size_t)bk * N + n0 + bn;

    auto issue_tile = [&](unsigned* Ad, unsigned* Bd, int kt) {
#pragma unroll
        for (int i = 0; i < 4; i++)
            cp_async16(&Ad[(am + i * 32) * A_ST + ak],
                       Aptr + (size_t)(i * 32) * K + kt);
#pragma unroll
        for (int i = 0; i < 2; i++)
            cp_async16(&Bd[(bk + i * 16) * B_ST + bn],
                       Bptr + (size_t)(kt + i * 16) * N);
        cp_async_commit();
    };

    issue_tile(As0, Bs0, 0);
    cp_async_wait0();
    __syncthreads();

    float acc[2][4][4];
#pragma unroll
    for (int mi = 0; mi < 2; mi++)
#pragma unroll
        for (int ni = 0; ni < 4; ni++)
#pragma unroll
            for (int q = 0; q < 4; q++) acc[mi][ni][q] = 0.f;

    int cur = 0;
    for (int kt = 0; kt < K; kt += 32) {
        const bool more = (kt + 32) < K;
        if (more)
            issue_tile(cur ? As0 : As1, cur ? Bs0 : Bs1, kt + 32);

        const unsigned* Ab = cur ? As1 : As0;
        const unsigned* Bb = cur ? Bs1 : Bs0;
#pragma unroll
        for (int kk = 0; kk < 32; kk += 8) {
            unsigned af[2][4], bf[4][2];
#pragma unroll
            for (int mi = 0; mi < 2; mi++) {
                const int row = wm + mi * 16 + lr;
                af[mi][0] = Ab[row * A_ST + kk + lc];
                af[mi][1] = Ab[(row + 8) * A_ST + kk + lc];
                af[mi][2] = Ab[row * A_ST + kk + 4 + lc];
                af[mi][3] = Ab[(row + 8) * A_ST + kk + 4 + lc];
            }
#pragma unroll
            for (int ni = 0; ni < 4; ni++) {
                const int col = wn + ni * 8 + lr;
                bf[ni][0] = Bb[(kk + lc) * B_ST + col];
                bf[ni][1] = Bb[(kk + 4 + lc) * B_ST + col];
            }
#pragma unroll
            for (int mi = 0; mi < 2; mi++)
#pragma unroll
                for (int ni = 0; ni < 4; ni++)
                    mma_tf32(acc[mi][ni], af[mi], bf[ni]);
        }

        if (more) {
            cp_async_wait0();
            __syncthreads();
            cur ^= 1;
        }
    }

    // epilogue
#pragma unroll
    for (int mi = 0; mi < 2; mi++) {
#pragma unroll
        for (int ni = 0; ni < 4; ni++) {
            const int row = m0 + wm + mi * 16 + lr;
            const int col = n0 + wn + ni * 8 + (lc << 1);
            float b0 = 0.f, b1 = 0.f;
            if (bias) { b0 = bias[col]; b1 = bias[col + 1]; }
            float2 o0, o1;
            o0.x = acc[mi][ni][0] + b0; o0.y = acc[mi][ni][1] + b1;
            o1.x = acc[mi][ni][2] + b0; o1.y = acc[mi][ni][3] + b1;
            *(float2*)&C[(size_t)row * N + col] = o0;
            *(float2*)&C[(size_t)(row + 8) * N + col] = o1;
        }
    }
}

// ========== small tf32 GEMM (128x64 tile) for the 64-col projections =========
__device__ __forceinline__ void gemm_body(
    const float* __restrict__ A, const float* __restrict__ B,
    const float* __restrict__ bias, float* __restrict__ C,
    int M, int N, int K)
{
    __shared__ unsigned As[128 * A_ST];
    __shared__ unsigned Bs[32 * B_ST];

    const int tid = threadIdx.x;
    const int lane = tid & 31, warp = tid >> 5;
    const int wm = (warp & 3) << 5;
    const int wn = (warp >> 2) << 5;
    const int m0 = blockIdx.y << 7, n0 = blockIdx.x << 6;
    const int lr = lane >> 2, lc = lane & 3;

    const int am = tid >> 3, ak = (tid & 7) << 2;
    const int bk = tid >> 4, bn = (tid & 15) << 2;

    const float* Aptr = A + (size_t)(m0 + am) * K + ak;
    const float* Bptr = B + (size_t)bk * N + n0 + bn;

    float4 ar[4], br[2];
#pragma unroll
    for (int i = 0; i < 4; i++) ar[i] = *(const float4*)(Aptr + (size_t)(i * 32) * K);
#pragma unroll
    for (int i = 0; i < 2; i++) br[i] = *(const float4*)(Bptr + (size_t)(i * 16) * N);

    float acc[2][4][4];
#pragma unroll
    for (int mi = 0; mi < 2; mi++)
#pragma unroll
        for (int ni = 0; ni < 4; ni++)
#pragma unroll
            for (int q = 0; q < 4; q++) acc[mi][ni][q] = 0.f;

    for (int kt = 0; kt < K; kt += 32) {
        __syncthreads();
#pragma unroll
        for (int i = 0; i < 4; i++) {
            unsigned* p = &As[(am + i * 32) * A_ST + ak];
            p[0] = f2tf(ar[i].x); p[1] = f2tf(ar[i].y);
            p[2] = f2tf(ar[i].z); p[3] = f2tf(ar[i].w);
        }
#pragma unroll
        for (int i = 0; i < 2; i++) {
            unsigned* p = &Bs[(bk + i * 16) * B_ST + bn];
            p[0] = f2tf(br[i].x); p[1] = f2tf(br[i].y);
            p[2] = f2tf(br[i].z); p[3] = f2tf(br[i].w);
        }
        __syncthreads();
        if (kt + 32 < K) {
#pragma unroll
            for (int i = 0; i < 4; i++)
                ar[i] = *(const float4*)(Aptr + (size_t)(i * 32) * K + (kt + 32));
#pragma unroll
            for (int i = 0; i < 2; i++)
                br[i] = *(const float4*)(Bptr + (size_t)(kt + 32 + i * 16) * N);
        }
#pragma unroll
        for (int kk = 0; kk < 32; kk += 8) {
            unsigned af[2][4], bf[4][2];
#pragma unroll
            for (int mi = 0; mi < 2; mi++) {
                const int row = wm + mi * 16 + lr;
                af[mi][0] = As[row * A_ST + kk + lc];
                af[mi][1] = As[(row + 8) * A_ST + kk + lc];
                af[mi][2] = As[row * A_ST + kk + 4 + lc];
                af[mi][3] = As[(row + 8) * A_ST + kk + 4 + lc];
            }
#pragma unroll
            for (int ni = 0; ni < 4; ni++) {
                const int col = wn + ni * 8 + lr;
                bf[ni][0] = Bs[(kk + lc) * B_ST + col];
                bf[ni][1] = Bs[(kk + 4 + lc) * B_ST + col];
            }
#pragma unroll
            for (int mi = 0; mi < 2; mi++)
#pragma unroll
                for (int ni = 0; ni < 4; ni++)
                    mma_tf32(acc[mi][ni], af[mi], bf[ni]);
        }
    }

#pragma unroll
    for (int mi = 0; mi < 2; mi++) {
#pragma unroll
        for (int ni = 0; ni < 4; ni++) {
            const int row = m0 + wm + mi * 16 + lr;
            const int col = n0 + wn + ni * 8 + (lc << 1);
            float b0 = 0.f, b1 = 0.f;
            if (bias) { b0 = bias[col]; b1 = bias[col + 1]; }
            float2 o0, o1;
            o0.x = acc[mi][ni][0] + b0; o0.y = acc[mi][ni][1] + b1;
            o1.x = acc[mi][ni][2] + b0; o1.y = acc[mi][ni][3] + b1;
            *(float2*)&C[(size_t)row * N + col] = o0;
            *(float2*)&C[(size_t)(row + 8) * N + col] = o1;
        }
    }
}

__global__ __launch_bounds__(256) void gemm_proj(
    const float* __restrict__ x,
    const float* __restrict__ w0, const float* __restrict__ w1,
    const float* __restrict__ w2, const float* __restrict__ w3)
{
    const float* B = (blockIdx.z == 0) ? w0 : (blockIdx.z == 1) ? w1
                   : (blockIdx.z == 2) ? w2 : w3;
    float* C = g_proj + (size_t)blockIdx.z * TT * 64;
    gemm_body(x, B, nullptr, C, TT, 64, DD);
}

// ------------- Plucker lines from projections --------------------------------
__global__ __launch_bounds__(256) void lines_kernel()
{
    const int idx = blockIdx.x * 256 + threadIdx.x;   // T*H
    const int h = idx & (HH - 1), t = idx >> 4;
    const float* P1 = g_proj;
    const float* P2 = g_proj + TT * 64;
    const float* R1 = g_proj + 2 * TT * 64;
    const float* R2 = g_proj + 3 * TT * 64;

    float a0 = 0.f, a1 = 0.f, a2 = 0.f, a3 = 0.f;
    if (t > 0) {
        const float* p = P1 + (size_t)(t - 1) * 64 + h * 4;
        a0 = p[0]; a1 = p[1]; a2 = p[2]; a3 = p[3];
    }
    const float* p2 = P2 + (size_t)t * 64 + h * 4;
    float b0 = p2[0], b1 = p2[1], b2 = p2[2], b3 = p2[3];

    float L0 = a0 * b1 - a1 * b0;
    float L1 = a0 * b2 - a2 * b0;
    float L2 = a0 * b3 - a3 * b0;
    float L3 = a1 * b2 - a2 * b1;
    float L4 = a1 * b3 - a3 * b1;
    float L5 = a2 * b3 - a3 * b2;
    float n = sqrtf(L0 * L0 + L1 * L1 + L2 * L2 + L3 * L3 + L4 * L4 + L5 * L5);
    float inv = 1.f / fmaxf(n, 1e-12f);
    float* jw = g_jw + h * 6 * TT;
    jw[0 * TT + t] =  L5 * inv;   // j = (L5,-L4,L3,L2,-L1,L0)
    jw[1 * TT + t] = -L4 * inv;
    jw[2 * TT + t] =  L3 * inv;
    jw[3 * TT + t] =  L2 * inv;
    jw[4 * TT + t] = -L1 * inv;
    jw[5 * TT + t] =  L0 * inv;

    const float* r1 = R1 + (size_t)t * 64 + h * 4;
    const float* r2 = R2 + (size_t)t * 64 + h * 4;
    a0 = r1[0]; a1 = r1[1]; a2 = r1[2]; a3 = r1[3];
    b0 = r2[0]; b1 = r2[1]; b2 = r2[2]; b3 = r2[3];
    L0 = a0 * b1 - a1 * b0;
    L1 = a0 * b2 - a2 * b0;
    L2 = a0 * b3 - a3 * b0;
    L3 = a1 * b2 - a2 * b1;
    L4 = a1 * b3 - a3 * b1;
    L5 = a2 * b3 - a3 * b2;
    n = sqrtf(L0 * L0 + L1 * L1 + L2 * L2 + L3 * L3 + L4 * L4 + L5 * L5);
    inv = 1.f / fmaxf(n, 1e-12f);
    float* rd = g_read + ((size_t)t * HH + h) * 6;
    rd[0] = L0 * inv; rd[1] = L1 * inv; rd[2] = L2 * inv;
    rd[3] = L3 * inv; rd[4] = L4 * inv; rd[5] = L5 * inv;
}

// ------------- mem_score / gram gate (O(T^2) strided, known-good) -------------
__global__ __launch_bounds__(128) void memscore(
    const float* __restrict__ decay_logits, const float* __restrict__ mem_scale)
{
    const int t = blockIdx.x, h = blockIdx.y, tid = threadIdx.x;
    const float* rd = g_read + ((size_t)t * HH + h) * 6;
    const float r0 = rd[0], r1 = rd[1], r2 = rd[2], r3 = rd[3], r4 = rd[4], r5 = rd[5];

    const float logit = decay_logits[h];
    const float decay = 1.f / (1.f + expf(-logit));
    const float dlog = logf(decay);
    float w = expf((float)(tid + 1) * dlog);
    const float d128 = expf(128.f * dlog);

    const float* base = g_jw + h * 6 * TT;
    float partial = 0.f;
    for (int s = t - 1 - tid; s >= 0; s -= 128) {
        float inc = r0 * base[s] + r1 * base[TT + s] + r2 * base[2 * TT + s]
                  + r3 * base[3 * TT + s] + r4 * base[4 * TT + s] + r5 * base[5 * TT + s];
        partial += inc * inc * w;
        w *= d128;
    }
#pragma unroll
    for (int o = 16; o > 0; o >>= 1) partial += __shfl_xor_sync(0xffffffffu, partial, o);
    __shared__ float red[4];
    if ((tid & 31) == 0) red[tid >> 5] = partial;
    __syncthreads();
    if (tid == 0) {
        float ms = red[0] + red[1] + red[2] + red[3];
        g_gate[h * TT + t] = 1.f / (1.f + expf(-ms * mem_scale[h]));
    }
}

// ------------- causal flash attention with FUSED K/V enhancement -------------
// tile_off selects the query-tile range; largest m0 launches first.
// K/V loader computes k_enh = k + gg*k_geo, v_enh = v + gg*v_geo inline
// (identical fp32 ops/order as the old enhance kernel -> bit-identical).
#define KS_ST 68
#define VS_ST 72
__global__ __launch_bounds__(128) void attn(int tile_off, const float* __restrict__ kv_gate_p)
{
    __shared__ unsigned Ks[64 * KS_ST];
    __shared__ unsigned Vs[64 * VS_ST];
    const int h = blockIdx.y;
    const int m0 = (tile_off + (int)gridDim.x - 1 - (int)blockIdx.x) << 6;
    const int tid = threadIdx.x, lane = tid & 31, warp = tid >> 5;
    const int lr = lane >> 2, lc = lane & 3;
    const int wm = warp << 4;
    const float kvg = kv_gate_p[0];

    for (int i = tid; i < 64 * 16; i += 128) {
        const int row = i >> 4, c4 = (i & 15) << 2;
        float4 v = *(const float4*)(g_qkv + (size_t)(m0 + row) * 3 * DD + h * 64 + c4);
        unsigned* p = &Ks[row * KS_ST + c4];
        p[0] = f2tf(v.x * 0.125f); p[1] = f2tf(v.y * 0.125f);
        p[2] = f2tf(v.z * 0.125f); p[3] = f2tf(v.w * 0.125f);
    }
    __syncthreads();
    unsigned qf[8][4];
#pragma unroll
    for (int kt = 0; kt < 8; kt++) {
        qf[kt][0] = Ks[(wm + lr) * KS_ST + kt * 8 + lc];
        qf[kt][1] = Ks[(wm + lr + 8) * KS_ST + kt * 8 + lc];
        qf[kt][2] = Ks[(wm + lr) * KS_ST + kt * 8 + 4 + lc];
        qf[kt][3] = Ks[(wm + lr + 8) * KS_ST + kt * 8 + 4 + lc];
    }

    float oacc[8][4];
#pragma unroll
    for (int ni = 0; ni < 8; ni++)
#pragma unroll
        for (int q = 0; q < 4; q++) oacc[ni][q] = 0.f;
    float mrun0 = -1e30f, mrun1 = -1e30f, lrun0 = 0.f, lrun1 = 0.f;

    for (int s0 = 0; s0 <= m0; s0 += 64) {
        __syncthreads();
        for (int i = tid; i < 64 * 16; i += 128) {
            const int row = i >> 4, c4 = (i & 15) << 2;
            const int t = s0 + row;
            const float gg = kvg * g_gate[h * TT + t];
            const size_t qb = (size_t)t * 3 * DD + h * 64 + c4;
            const size_t gb = (size_t)t * 2 * DD + h * 64 + c4;
            float4 kv = *(const float4*)(g_qkv + qb + DD);
            float4 kg = *(const float4*)(g_kvgeo + gb);
            kv.x += gg * kg.x; kv.y += gg * kg.y;
            kv.z += gg * kg.z; kv.w += gg * kg.w;
            unsigned* pk = &Ks[row * KS_ST + c4];
            pk[0] = f2tf(kv.x); pk[1] = f2tf(kv.y); pk[2] = f2tf(kv.z); pk[3] = f2tf(kv.w);
            float4 vv = *(const float4*)(g_qkv + qb + 2 * DD);
            float4 vg = *(const float4*)(g_kvgeo + gb + DD);
            vv.x += gg * vg.x; vv.y += gg * vg.y;
            vv.z += gg * vg.z; vv.w += gg * vg.w;
            unsigned* pv = &Vs[row * VS_ST + c4];
            pv[0] = f2tf(vv.x); pv[1] = f2tf(vv.y); pv[2] = f2tf(vv.z); pv[3] = f2tf(vv.w);
        }
        __syncthreads();

        float sacc[8][4];
#pragma unroll
        for (int ni = 0; ni < 8; ni++)
#pragma unroll
            for (int q = 0; q < 4; q++) sacc[ni][q] = 0.f;
#pragma unroll
        for (int kt = 0; kt < 8; kt++) {
            unsigned bf[8][2];
#pragma unroll
            for (int ni = 0; ni < 8; ni++) {
                const int col = ni * 8 + lr;
                bf[ni][0] = Ks[col * KS_ST + kt * 8 + lc];
                bf[ni][1] = Ks[col * KS_ST + kt * 8 + 4 + lc];
            }
#pragma unroll
            for (int ni = 0; ni < 8; ni++) mma_tf32(sacc[ni], qf[kt], bf[ni]);
        }

        if (s0 == m0) {
            const int r0 = wm + lr, r1 = r0 + 8;
#pragma unroll
            for (int ni = 0; ni < 8; ni++) {
                const int c0 = ni * 8 + (lc << 1), c1 = c0 + 1;
                if (c0 > r0) sacc[ni][0] = -1e30f;
                if (c1 > r0) sacc[ni][1] = -1e30f;
                if (c0 > r1) sacc[ni][2] = -1e30f;
                if (c1 > r1) sacc[ni][3] = -1e30f;
            }
        }

        float mx0 = -1e30f, mx1 = -1e30f;
#pragma unroll
        for (int ni = 0; ni < 8; ni++) {
            mx0 = fmaxf(mx0, fmaxf(sacc[ni][0], sacc[ni][1]));
            mx1 = fmaxf(mx1, fmaxf(sacc[ni][2], sacc[ni][3]));
        }
        mx0 = fmaxf(mx0, __shfl_xor_sync(0xffffffffu, mx0, 1));
        mx0 = fmaxf(mx0, __shfl_xor_sync(0xffffffffu, mx0, 2));
        mx1 = fmaxf(mx1, __shfl_xor_sync(0xffffffffu, mx1, 1));
        mx1 = fmaxf(mx1, __shfl_xor_sync(0xffffffffu, mx1, 2));

        const float mnew0 = fmaxf(mrun0, mx0), mnew1 = fmaxf(mrun1, mx1);
        const float corr0 = __expf(mrun0 - mnew0), corr1 = __expf(mrun1 - mnew1);
        mrun0 = mnew0; mrun1 = mnew1;

        __syncthreads();

        float l0 = 0.f, l1 = 0.f;
#pragma unroll
        for (int ni = 0; ni < 8; ni++) {
            const float p0 = __expf(sacc[ni][0] - mnew0);
            const float p1 = __expf(sacc[ni][1] - mnew0);
            const float p2 = __expf(sacc[ni][2] - mnew1);
            const float p3 = __expf(sacc[ni][3] - mnew1);
            l0 += p0 + p1; l1 += p2 + p3;
            const int c = ni * 8 + (lc << 1);
            Ks[(wm + lr) * KS_ST + c]     = f2tf(p0);
            Ks[(wm + lr) * KS_ST + c + 1] = f2tf(p1);
            Ks[(wm + lr + 8) * KS_ST + c]     = f2tf(p2);
            Ks[(wm + lr + 8) * KS_ST + c + 1] = f2tf(p3);
        }
        l0 += __shfl_xor_sync(0xffffffffu, l0, 1);
        l0 += __shfl_xor_sync(0xffffffffu, l0, 2);
        l1 += __shfl_xor_sync(0xffffffffu, l1, 1);
        l1 += __shfl_xor_sync(0xffffffffu, l1, 2);
        lrun0 = lrun0 * corr0 + l0;
        lrun1 = lrun1 * corr1 + l1;
#pragma unroll
        for (int ni = 0; ni < 8; ni++) {
            oacc[ni][0] *= corr0; oacc[ni][1] *= corr0;
            oacc[ni][2] *= corr1; oacc[ni][3] *= corr1;
        }
        __syncwarp();

#pragma unroll
        for (int kt = 0; kt < 8; kt++) {
            unsigned af[4];
            af[0] = Ks[(wm + lr) * KS_ST + kt * 8 + lc];
            af[1] = Ks[(wm + lr + 8) * KS_ST + kt * 8 + lc];
            af[2] = Ks[(wm + lr) * KS_ST + kt * 8 + 4 + lc];
            af[3] = Ks[(wm + lr + 8) * KS_ST + kt * 8 + 4 + lc];
            unsigned bf[8][2];
#pragma unroll
            for (int ni = 0; ni < 8; ni++) {
                const int col = ni * 8 + lr;
                bf[ni][0] = Vs[(kt * 8 + lc) * VS_ST + col];
                bf[ni][1] = Vs[(kt * 8 + 4 + lc) * VS_ST + col];
            }
#pragma unroll
            for (int ni = 0; ni < 8; ni++) mma_tf32(oacc[ni], af, bf[ni]);
        }
    }

    const float inv0 = 1.f / lrun0, inv1 = 1.f / lrun1;
    const int r0 = m0 + wm + lr;
#pragma unroll
    for (int ni = 0; ni < 8; ni++) {
        const int c = h * 64 + ni * 8 + (lc << 1);
        float2 o0, o1;
        o0.x = __uint_as_float(f2tf(oacc[ni][0] * inv0));
        o0.y = __uint_as_float(f2tf(oacc[ni][1] * inv0));
        o1.x = __uint_as_float(f2tf(oacc[ni][2] * inv1));
        o1.y = __uint_as_float(f2tf(oacc[ni][3] * inv1));
        *(float2*)&g_attno[(size_t)r0 * DD + c] = o0;
        *(float2*)&g_attno[(size_t)(r0 + 8) * DD + c] = o1;
    }
}

// -----------------------------------------------------------------------------
extern "C" void kernel_launch(void* const* d_in, const int* in_sizes, int n_in,
                              void* d_out, int out_size)
{
    const float* x            = (const float*)d_in[0];
    const float* qkv_w        = (const float*)d_in[1];
    const float* qkv_b        = (const float*)d_in[2];
    const float* w1_write     = (const float*)d_in[3];
    const float* w2_write     = (const float*)d_in[4];
    const float* w1_read      = (const float*)d_in[5];
    const float* w2_read      = (const float*)d_in[6];
    const float* kv_geo_w     = (const float*)d_in[7];
    const float* out_w        = (const float*)d_in[8];
    const float* out_b        = (const float*)d_in[9];
    const float* kv_gate      = (const float*)d_in[10];
    const float* mem_scale    = (const float*)d_in[11];
    const float* decay_logits = (const float*)d_in[12];
    float* out = (float*)d_out;

    float *p_qkv, *p_kvgeo, *p_attno, *p_xr, *p_qwr, *p_gwr, *p_owr;
    cudaGetSymbolAddress((void**)&p_qkv,   g_qkv);
    cudaGetSymbolAddress((void**)&p_kvgeo, g_kvgeo);
    cudaGetSymbolAddress((void**)&p_attno, g_attno);
    cudaGetSymbolAddress((void**)&p_xr,    g_xr);
    cudaGetSymbolAddress((void**)&p_qwr,   g_qwr);
    cudaGetSymbolAddress((void**)&p_gwr,   g_gwr);
    cudaGetSymbolAddress((void**)&p_owr,   g_owr);

    cudaFuncSetAttribute(gemm_tf32, cudaFuncAttributeMaxDynamicSharedMemorySize,
                         GEMM_SMEM_BYTES);

    // One-time creation of the side stream + fork/join events.
    static cudaStream_t s1 = nullptr;
    static cudaEvent_t ev_fork = nullptr, ev_join = nullptr;
    static cudaEvent_t ev_attn = nullptr, ev_tail = nullptr;
    if (s1 == nullptr) {
        cudaStreamCreateWithFlags(&s1, cudaStreamNonBlocking);
        cudaEventCreateWithFlags(&ev_fork, cudaEventDisableTiming);
        cudaEventCreateWithFlags(&ev_join, cudaEventDisableTiming);
        cudaEventCreateWithFlags(&ev_attn, cudaEventDisableTiming);
        cudaEventCreateWithFlags(&ev_tail, cudaEventDisableTiming);
    }

    // ---- main stream (capture/legacy stream, 0): round x, fork ----
    round_tf32<<<(TT * DD / 4) / 256, 256>>>((const float4*)x, (float4*)p_xr);
    cudaEventRecord(ev_fork, 0);
    cudaStreamWaitEvent(s1, ev_fork, 0);

    // ---- side chain on s1: proj -> lines -> memscore, plus out_w rounding ----
    gemm_proj<<<dim3(1, TT / 128, 4), 256, 0, s1>>>(p_xr, w1_write, w2_write, w1_read, w2_read);
    lines_kernel<<<(TT * HH) / 256, 256, 0, s1>>>();
    memscore<<<dim3(TT, HH), 128, 0, s1>>>(decay_logits, mem_scale);
    round_tf32<<<(DD * DD / 4) / 256, 256, 0, s1>>>((const float4*)out_w, (float4*)p_owr);
    cudaEventRecord(ev_join, s1);

    // ---- main chain on stream 0: weight rounding + the two big GEMMs ----
    round_tf32<<<(DD * 3 * DD / 4) / 256, 256>>>((const float4*)qkv_w, (float4*)p_qwr);
    round_tf32<<<(DD * 2 * DD / 4) / 256, 256>>>((const float4*)kv_geo_w, (float4*)p_gwr);
    gemm_tf32<<<dim3(3072 / 64, TT / 128), 256, GEMM_SMEM_BYTES>>>(p_xr, p_qwr, qkv_b, p_qkv, TT, 3072, DD);
    gemm_tf32<<<dim3(2048 / 64, TT / 128), 256, GEMM_SMEM_BYTES>>>(p_xr, p_gwr, nullptr, p_kvgeo, TT, 2048, DD);

    // ---- join: attn needs gate (s1) + qkv/kvgeo (s0); enhance is fused ----
    cudaStreamWaitEvent(0, ev_join, 0);

    // ---- fork 2: split attn + out GEMM into low/high halves --------------
    cudaEventRecord(ev_attn, 0);
    cudaStreamWaitEvent(s1, ev_attn, 0);
    // s1: short half (query tiles 0..15) then out rows [0, 1024)
    attn<<<dim3(16, HH), 128, 0, s1>>>(0, kv_gate);
    gemm_tf32<<<dim3(DD / 64, 8), 256, GEMM_SMEM_BYTES, s1>>>(p_attno, p_owr, out_b, out, 1024, DD, DD);
    cudaEventRecord(ev_tail, s1);
    // stream 0: long half (query tiles 16..31) then out rows [1024, 2048)
    attn<<<dim3(16, HH), 128>>>(16, kv_gate);
    gemm_tf32<<<dim3(DD / 64, 8), 256, GEMM_SMEM_BYTES>>>(p_attno + (size_t)1024 * DD, p_owr, out_b, out + (size_t)1024 * DD, 1024, DD, DD);
    cudaStreamWaitEvent(0, ev_tail, 0);
}

// round 17
// speedup vs baseline: 1.1312x; 1.1312x over previous
#include <cuda_runtime.h>

#define TT 2048
#define DD 1024
#define HH 16

// ---------------- scratch (static device globals; no allocations) -------------
__device__ float g_qkv[TT * 3 * DD];     // [t][3*1024]  (q|k|v per token)
__device__ float g_kvgeo[TT * 2 * DD];   // [t][2*1024]  (k_geo|v_geo)
__device__ float g_proj[4 * TT * 64];    // P1|P2|R1|R2, each [t][64]
__device__ float g_jw[HH * 6 * TT];      // [h][c][t]    J6-applied write lines
__device__ float g_read[TT * HH * 6];    // [t][h][c]    read lines
__device__ float g_gate[HH * TT];        // [h][t]       gram gate
__device__ float g_kenh[HH * TT * 64];   // [h][t][d]
__device__ float g_venh[HH * TT * 64];   // [h][t][d]
__device__ float g_attno[TT * DD];       // [t][h*64+d]  attention output (tf32-rounded)
// tf32-pre-rounded operand copies for the cp.async GEMMs
__device__ float g_xr[TT * DD];          // rounded x
__device__ float g_qwr[DD * 3 * DD];     // rounded qkv_w
__device__ float g_gwr[DD * 2 * DD];     // rounded kv_geo_w
__device__ float g_owr[DD * DD];         // rounded out_w

// ---------------- tf32 helpers ----------------------------------------------
__device__ __forceinline__ unsigned f2tf(float f) {
    unsigned r;
    asm("cvt.rna.tf32.f32 %0, %1;" : "=r"(r) : "f"(f));
    return r;
}

__device__ __forceinline__ void mma_tf32(float* c, const unsigned* a, const unsigned* b) {
    asm volatile(
        "mma.sync.aligned.m16n8k8.row.col.f32.tf32.tf32.f32 "
        "{%0,%1,%2,%3}, {%4,%5,%6,%7}, {%8,%9}, {%0,%1,%2,%3};"
        : "+f"(c[0]), "+f"(c[1]), "+f"(c[2]), "+f"(c[3])
        : "r"(a[0]), "r"(a[1]), "r"(a[2]), "r"(a[3]), "r"(b[0]), "r"(b[1]));
}

__device__ __forceinline__ void cp_async16(void* smem_dst, const void* gmem_src) {
    unsigned dst = (unsigned)__cvta_generic_to_shared(smem_dst);
    asm volatile("cp.async.ca.shared.global [%0], [%1], 16;"
                 :: "r"(dst), "l"(gmem_src));
}
__device__ __forceinline__ void cp_async_commit() {
    asm volatile("cp.async.commit_group;" ::: "memory");
}
__device__ __forceinline__ void cp_async_wait0() {
    asm volatile("cp.async.wait_group 0;" ::: "memory");
}

// ---------------- tf32 pre-rounding (RNA), float4 vectorized -----------------
__global__ __launch_bounds__(256) void round_tf32(
    const float4* __restrict__ src, float4* __restrict__ dst)
{
    const int i = blockIdx.x * 256 + threadIdx.x;
    float4 v = src[i];
    float4 o;
    o.x = __uint_as_float(f2tf(v.x));
    o.y = __uint_as_float(f2tf(v.y));
    o.z = __uint_as_float(f2tf(v.z));
    o.w = __uint_as_float(f2tf(v.w));
    dst[i] = o;
}

// ========== big tf32 GEMM: cp.async double buffer, pre-rounded inputs ========
#define A_ST 36
#define B_ST 72
#define A_WORDS (128 * A_ST)     // 4608
#define B_WORDS (32 * B_ST)      // 2304
#define GEMM_SMEM_BYTES (2 * (A_WORDS + B_WORDS) * 4)   // 55296

__global__ __launch_bounds__(256) void gemm_tf32(
    const float* __restrict__ A, const float* __restrict__ B,
    const float* __restrict__ bias, float* __restrict__ C,
    int M, int N, int K)
{
    extern __shared__ unsigned sm[];
    unsigned* const As0 = sm;
    unsigned* const As1 = sm + A_WORDS;
    unsigned* const Bs0 = sm + 2 * A_WORDS;
    unsigned* const Bs1 = sm + 2 * A_WORDS + B_WORDS;

    const int tid = threadIdx.x;
    const int lane = tid & 31, warp = tid >> 5;
    const int wm = (warp & 3) << 5;
    const int wn = (warp >> 2) << 5;
    const int m0 = blockIdx.y << 7, n0 = blockIdx.x << 6;
    const int lr = lane >> 2, lc = lane & 3;

    const int am = tid >> 3, ak = (tid & 7) << 2;
    const int bk = tid >> 4, bn = (tid & 15) << 2;

    const float* Aptr = A + (size_t)(m0 + am) * K + ak;
    const float* Bptr = B + (size_t)bk * N + n0 + bn;

    auto issue_tile = [&](unsigned* Ad, unsigned* Bd, int kt) {
#pragma unroll
        for (int i = 0; i < 4; i++)
            cp_async16(&Ad[(am + i * 32) * A_ST + ak],
                       Aptr + (size_t)(i * 32) * K + kt);
#pragma unroll
        for (int i = 0; i < 2; i++)
            cp_async16(&Bd[(bk + i * 16) * B_ST + bn],
                       Bptr + (size_t)(kt + i * 16) * N);
        cp_async_commit();
    };

    issue_tile(As0, Bs0, 0);
    cp_async_wait0();
    __syncthreads();

    float acc[2][4][4];
#pragma unroll
    for (int mi = 0; mi < 2; mi++)
#pragma unroll
        for (int ni = 0; ni < 4; ni++)
#pragma unroll
            for (int q = 0; q < 4; q++) acc[mi][ni][q] = 0.f;

    int cur = 0;
    for (int kt = 0; kt < K; kt += 32) {
        const bool more = (kt + 32) < K;
        if (more)
            issue_tile(cur ? As0 : As1, cur ? Bs0 : Bs1, kt + 32);

        const unsigned* Ab = cur ? As1 : As0;
        const unsigned* Bb = cur ? Bs1 : Bs0;
#pragma unroll
        for (int kk = 0; kk < 32; kk += 8) {
            unsigned af[2][4], bf[4][2];
#pragma unroll
            for (int mi = 0; mi < 2; mi++) {
                const int row = wm + mi * 16 + lr;
                af[mi][0] = Ab[row * A_ST + kk + lc];
                af[mi][1] = Ab[(row + 8) * A_ST + kk + lc];
                af[mi][2] = Ab[row * A_ST + kk + 4 + lc];
                af[mi][3] = Ab[(row + 8) * A_ST + kk + 4 + lc];
            }
#pragma unroll
            for (int ni = 0; ni < 4; ni++) {
                const int col = wn + ni * 8 + lr;
                bf[ni][0] = Bb[(kk + lc) * B_ST + col];
                bf[ni][1] = Bb[(kk + 4 + lc) * B_ST + col];
            }
#pragma unroll
            for (int mi = 0; mi < 2; mi++)
#pragma unroll
                for (int ni = 0; ni < 4; ni++)
                    mma_tf32(acc[mi][ni], af[mi], bf[ni]);
        }

        if (more) {
            cp_async_wait0();
            __syncthreads();
            cur ^= 1;
        }
    }

    // epilogue
#pragma unroll
    for (int mi = 0; mi < 2; mi++) {
#pragma unroll
        for (int ni = 0; ni < 4; ni++) {
            const int row = m0 + wm + mi * 16 + lr;
            const int col = n0 + wn + ni * 8 + (lc << 1);
            float b0 = 0.f, b1 = 0.f;
            if (bias) { b0 = bias[col]; b1 = bias[col + 1]; }
            float2 o0, o1;
            o0.x = acc[mi][ni][0] + b0; o0.y = acc[mi][ni][1] + b1;
            o1.x = acc[mi][ni][2] + b0; o1.y = acc[mi][ni][3] + b1;
            *(float2*)&C[(size_t)row * N + col] = o0;
            *(float2*)&C[(size_t)(row + 8) * N + col] = o1;
        }
    }
}

// ========== small tf32 GEMM (128x64 tile) for the 64-col projections =========
__device__ __forceinline__ void gemm_body(
    const float* __restrict__ A, const float* __restrict__ B,
    const float* __restrict__ bias, float* __restrict__ C,
    int M, int N, int K)
{
    __shared__ unsigned As[128 * A_ST];
    __shared__ unsigned Bs[32 * B_ST];

    const int tid = threadIdx.x;
    const int lane = tid & 31, warp = tid >> 5;
    const int wm = (warp & 3) << 5;
    const int wn = (warp >> 2) << 5;
    const int m0 = blockIdx.y << 7, n0 = blockIdx.x << 6;
    const int lr = lane >> 2, lc = lane & 3;

    const int am = tid >> 3, ak = (tid & 7) << 2;
    const int bk = tid >> 4, bn = (tid & 15) << 2;

    const float* Aptr = A + (size_t)(m0 + am) * K + ak;
    const float* Bptr = B + (size_t)bk * N + n0 + bn;

    float4 ar[4], br[2];
#pragma unroll
    for (int i = 0; i < 4; i++) ar[i] = *(const float4*)(Aptr + (size_t)(i * 32) * K);
#pragma unroll
    for (int i = 0; i < 2; i++) br[i] = *(const float4*)(Bptr + (size_t)(i * 16) * N);

    float acc[2][4][4];
#pragma unroll
    for (int mi = 0; mi < 2; mi++)
#pragma unroll
        for (int ni = 0; ni < 4; ni++)
#pragma unroll
            for (int q = 0; q < 4; q++) acc[mi][ni][q] = 0.f;

    for (int kt = 0; kt < K; kt += 32) {
        __syncthreads();
#pragma unroll
        for (int i = 0; i < 4; i++) {
            unsigned* p = &As[(am + i * 32) * A_ST + ak];
            p[0] = f2tf(ar[i].x); p[1] = f2tf(ar[i].y);
            p[2] = f2tf(ar[i].z); p[3] = f2tf(ar[i].w);
        }
#pragma unroll
        for (int i = 0; i < 2; i++) {
            unsigned* p = &Bs[(bk + i * 16) * B_ST + bn];
            p[0] = f2tf(br[i].x); p[1] = f2tf(br[i].y);
            p[2] = f2tf(br[i].z); p[3] = f2tf(br[i].w);
        }
        __syncthreads();
        if (kt + 32 < K) {
#pragma unroll
            for (int i = 0; i < 4; i++)
                ar[i] = *(const float4*)(Aptr + (size_t)(i * 32) * K + (kt + 32));
#pragma unroll
            for (int i = 0; i < 2; i++)
                br[i] = *(const float4*)(Bptr + (size_t)(kt + 32 + i * 16) * N);
        }
#pragma unroll
        for (int kk = 0; kk < 32; kk += 8) {
            unsigned af[2][4], bf[4][2];
#pragma unroll
            for (int mi = 0; mi < 2; mi++) {
                const int row = wm + mi * 16 + lr;
                af[mi][0] = As[row * A_ST + kk + lc];
                af[mi][1] = As[(row + 8) * A_ST + kk + lc];
                af[mi][2] = As[row * A_ST + kk + 4 + lc];
                af[mi][3] = As[(row + 8) * A_ST + kk + 4 + lc];
            }
#pragma unroll
            for (int ni = 0; ni < 4; ni++) {
                const int col = wn + ni * 8 + lr;
                bf[ni][0] = Bs[(kk + lc) * B_ST + col];
                bf[ni][1] = Bs[(kk + 4 + lc) * B_ST + col];
            }
#pragma unroll
            for (int mi = 0; mi < 2; mi++)
#pragma unroll
                for (int ni = 0; ni < 4; ni++)
                    mma_tf32(acc[mi][ni], af[mi], bf[ni]);
        }
    }

#pragma unroll
    for (int mi = 0; mi < 2; mi++) {
#pragma unroll
        for (int ni = 0; ni < 4; ni++) {
            const int row = m0 + wm + mi * 16 + lr;
            const int col = n0 + wn + ni * 8 + (lc << 1);
            float b0 = 0.f, b1 = 0.f;
            if (bias) { b0 = bias[col]; b1 = bias[col + 1]; }
            float2 o0, o1;
            o0.x = acc[mi][ni][0] + b0; o0.y = acc[mi][ni][1] + b1;
            o1.x = acc[mi][ni][2] + b0; o1.y = acc[mi][ni][3] + b1;
            *(float2*)&C[(size_t)row * N + col] = o0;
            *(float2*)&C[(size_t)(row + 8) * N + col] = o1;
        }
    }
}

__global__ __launch_bounds__(256) void gemm_proj(
    const float* __restrict__ x,
    const float* __restrict__ w0, const float* __restrict__ w1,
    const float* __restrict__ w2, const float* __restrict__ w3)
{
    const float* B = (blockIdx.z == 0) ? w0 : (blockIdx.z == 1) ? w1
                   : (blockIdx.z == 2) ? w2 : w3;
    float* C = g_proj + (size_t)blockIdx.z * TT * 64;
    gemm_body(x, B, nullptr, C, TT, 64, DD);
}

// ------------- Plucker lines from projections --------------------------------
__global__ __launch_bounds__(256) void lines_kernel()
{
    const int idx = blockIdx.x * 256 + threadIdx.x;   // T*H
    const int h = idx & (HH - 1), t = idx >> 4;
    const float* P1 = g_proj;
    const float* P2 = g_proj + TT * 64;
    const float* R1 = g_proj + 2 * TT * 64;
    const float* R2 = g_proj + 3 * TT * 64;

    float a0 = 0.f, a1 = 0.f, a2 = 0.f, a3 = 0.f;
    if (t > 0) {
        const float* p = P1 + (size_t)(t - 1) * 64 + h * 4;
        a0 = p[0]; a1 = p[1]; a2 = p[2]; a3 = p[3];
    }
    const float* p2 = P2 + (size_t)t * 64 + h * 4;
    float b0 = p2[0], b1 = p2[1], b2 = p2[2], b3 = p2[3];

    float L0 = a0 * b1 - a1 * b0;
    float L1 = a0 * b2 - a2 * b0;
    float L2 = a0 * b3 - a3 * b0;
    float L3 = a1 * b2 - a2 * b1;
    float L4 = a1 * b3 - a3 * b1;
    float L5 = a2 * b3 - a3 * b2;
    float n = sqrtf(L0 * L0 + L1 * L1 + L2 * L2 + L3 * L3 + L4 * L4 + L5 * L5);
    float inv = 1.f / fmaxf(n, 1e-12f);
    float* jw = g_jw + h * 6 * TT;
    jw[0 * TT + t] =  L5 * inv;   // j = (L5,-L4,L3,L2,-L1,L0)
    jw[1 * TT + t] = -L4 * inv;
    jw[2 * TT + t] =  L3 * inv;
    jw[3 * TT + t] =  L2 * inv;
    jw[4 * TT + t] = -L1 * inv;
    jw[5 * TT + t] =  L0 * inv;

    const float* r1 = R1 + (size_t)t * 64 + h * 4;
    const float* r2 = R2 + (size_t)t * 64 + h * 4;
    a0 = r1[0]; a1 = r1[1]; a2 = r1[2]; a3 = r1[3];
    b0 = r2[0]; b1 = r2[1]; b2 = r2[2]; b3 = r2[3];
    L0 = a0 * b1 - a1 * b0;
    L1 = a0 * b2 - a2 * b0;
    L2 = a0 * b3 - a3 * b0;
    L3 = a1 * b2 - a2 * b1;
    L4 = a1 * b3 - a3 * b1;
    L5 = a2 * b3 - a3 * b2;
    n = sqrtf(L0 * L0 + L1 * L1 + L2 * L2 + L3 * L3 + L4 * L4 + L5 * L5);
    inv = 1.f / fmaxf(n, 1e-12f);
    float* rd = g_read + ((size_t)t * HH + h) * 6;
    rd[0] = L0 * inv; rd[1] = L1 * inv; rd[2] = L2 * inv;
    rd[3] = L3 * inv; rd[4] = L4 * inv; rd[5] = L5 * inv;
}

// ------------- mem_score / gram gate (O(T^2) strided, known-good) -------------
__global__ __launch_bounds__(128) void memscore(
    const float* __restrict__ decay_logits, const float* __restrict__ mem_scale)
{
    const int t = blockIdx.x, h = blockIdx.y, tid = threadIdx.x;
    const float* rd = g_read + ((size_t)t * HH + h) * 6;
    const float r0 = rd[0], r1 = rd[1], r2 = rd[2], r3 = rd[3], r4 = rd[4], r5 = rd[5];

    const float logit = decay_logits[h];
    const float decay = 1.f / (1.f + expf(-logit));
    const float dlog = logf(decay);
    float w = expf((float)(tid + 1) * dlog);
    const float d128 = expf(128.f * dlog);

    const float* base = g_jw + h * 6 * TT;
    float partial = 0.f;
    for (int s = t - 1 - tid; s >= 0; s -= 128) {
        float inc = r0 * base[s] + r1 * base[TT + s] + r2 * base[2 * TT + s]
                  + r3 * base[3 * TT + s] + r4 * base[4 * TT + s] + r5 * base[5 * TT + s];
        partial += inc * inc * w;
        w *= d128;
    }
#pragma unroll
    for (int o = 16; o > 0; o >>= 1) partial += __shfl_xor_sync(0xffffffffu, partial, o);
    __shared__ float red[4];
    if ((tid & 31) == 0) red[tid >> 5] = partial;
    __syncthreads();
    if (tid == 0) {
        float ms = red[0] + red[1] + red[2] + red[3];
        g_gate[h * TT + t] = 1.f / (1.f + expf(-ms * mem_scale[h]));
    }
}

// ------------- k_enh / v_enh assembly ([h][t][d] layout, float4) -------------
__global__ __launch_bounds__(256) void enhance(const float* __restrict__ kv_gate_p)
{
    const int idx = blockIdx.x * 256 + threadIdx.x;  // over H*T*16 float4s
    const int d4 = idx & 15, t = (idx >> 4) & (TT - 1), h = idx >> 15;
    const float gg = kv_gate_p[0] * g_gate[h * TT + t];
    const float4 kg = *(const float4*)&g_kvgeo[(size_t)t * 2 * DD + h * 64 + d4 * 4];
    const float4 vg = *(const float4*)&g_kvgeo[(size_t)t * 2 * DD + DD + h * 64 + d4 * 4];
    const float4 kv = *(const float4*)&g_qkv[(size_t)t * 3 * DD + DD + h * 64 + d4 * 4];
    const float4 vv = *(const float4*)&g_qkv[(size_t)t * 3 * DD + 2 * DD + h * 64 + d4 * 4];
    float4 ko, vo;
    ko.x = kv.x + gg * kg.x; ko.y = kv.y + gg * kg.y;
    ko.z = kv.z + gg * kg.z; ko.w = kv.w + gg * kg.w;
    vo.x = vv.x + gg * vg.x; vo.y = vv.y + gg * vg.y;
    vo.z = vv.z + gg * vg.z; vo.w = vv.w + gg * vg.w;
    *(float4*)&g_kenh[idx * 4] = ko;
    *(float4*)&g_venh[idx * 4] = vo;
}

// ------------- causal flash attention, tf32 tensor cores (64-row tiles) ------
#define KS_ST 68
#define VS_ST 72
__global__ __launch_bounds__(128) void attn(int tile_off)
{
    __shared__ unsigned Ks[64 * KS_ST];
    __shared__ unsigned Vs[64 * VS_ST];
    const int h = blockIdx.y;
    const int m0 = (tile_off + (int)gridDim.x - 1 - (int)blockIdx.x) << 6;
    const int tid = threadIdx.x, lane = tid & 31, warp = tid >> 5;
    const int lr = lane >> 2, lc = lane & 3;
    const int wm = warp << 4;

    for (int i = tid; i < 64 * 16; i += 128) {
        const int row = i >> 4, c4 = (i & 15) << 2;
        float4 v = *(const float4*)(g_qkv + (size_t)(m0 + row) * 3 * DD + h * 64 + c4);
        unsigned* p = &Ks[row * KS_ST + c4];
        p[0] = f2tf(v.x * 0.125f); p[1] = f2tf(v.y * 0.125f);
        p[2] = f2tf(v.z * 0.125f); p[3] = f2tf(v.w * 0.125f);
    }
    __syncthreads();
    unsigned qf[8][4];
#pragma unroll
    for (int kt = 0; kt < 8; kt++) {
        qf[kt][0] = Ks[(wm + lr) * KS_ST + kt * 8 + lc];
        qf[kt][1] = Ks[(wm + lr + 8) * KS_ST + kt * 8 + lc];
        qf[kt][2] = Ks[(wm + lr) * KS_ST + kt * 8 + 4 + lc];
        qf[kt][3] = Ks[(wm + lr + 8) * KS_ST + kt * 8 + 4 + lc];
    }

    float oacc[8][4];
#pragma unroll
    for (int ni = 0; ni < 8; ni++)
#pragma unroll
        for (int q = 0; q < 4; q++) oacc[ni][q] = 0.f;
    float mrun0 = -1e30f, mrun1 = -1e30f, lrun0 = 0.f, lrun1 = 0.f;

    for (int s0 = 0; s0 <= m0; s0 += 64) {
        __syncthreads();
        for (int i = tid; i < 64 * 16; i += 128) {
            const int row = i >> 4, c4 = (i & 15) << 2;
            const size_t base = ((size_t)(h * TT + s0 + row)) << 6;
            float4 kv = *(const float4*)(g_kenh + base + c4);
            unsigned* pk = &Ks[row * KS_ST + c4];
            pk[0] = f2tf(kv.x); pk[1] = f2tf(kv.y); pk[2] = f2tf(kv.z); pk[3] = f2tf(kv.w);
            float4 vv = *(const float4*)(g_venh + base + c4);
            unsigned* pv = &Vs[row * VS_ST + c4];
            pv[0] = f2tf(vv.x); pv[1] = f2tf(vv.y); pv[2] = f2tf(vv.z); pv[3] = f2tf(vv.w);
        }
        __syncthreads();

        float sacc[8][4];
#pragma unroll
        for (int ni = 0; ni < 8; ni++)
#pragma unroll
            for (int q = 0; q < 4; q++) sacc[ni][q] = 0.f;
#pragma unroll
        for (int kt = 0; kt < 8; kt++) {
            unsigned bf[8][2];
#pragma unroll
            for (int ni = 0; ni < 8; ni++) {
                const int col = ni * 8 + lr;
                bf[ni][0] = Ks[col * KS_ST + kt * 8 + lc];
                bf[ni][1] = Ks[col * KS_ST + kt * 8 + 4 + lc];
            }
#pragma unroll
            for (int ni = 0; ni < 8; ni++) mma_tf32(sacc[ni], qf[kt], bf[ni]);
        }

        if (s0 == m0) {
            const int r0 = wm + lr, r1 = r0 + 8;
#pragma unroll
            for (int ni = 0; ni < 8; ni++) {
                const int c0 = ni * 8 + (lc << 1), c1 = c0 + 1;
                if (c0 > r0) sacc[ni][0] = -1e30f;
                if (c1 > r0) sacc[ni][1] = -1e30f;
                if (c0 > r1) sacc[ni][2] = -1e30f;
                if (c1 > r1) sacc[ni][3] = -1e30f;
            }
        }

        float mx0 = -1e30f, mx1 = -1e30f;
#pragma unroll
        for (int ni = 0; ni < 8; ni++) {
            mx0 = fmaxf(mx0, fmaxf(sacc[ni][0], sacc[ni][1]));
            mx1 = fmaxf(mx1, fmaxf(sacc[ni][2], sacc[ni][3]));
        }
        mx0 = fmaxf(mx0, __shfl_xor_sync(0xffffffffu, mx0, 1));
        mx0 = fmaxf(mx0, __shfl_xor_sync(0xffffffffu, mx0, 2));
        mx1 = fmaxf(mx1, __shfl_xor_sync(0xffffffffu, mx1, 1));
        mx1 = fmaxf(mx1, __shfl_xor_sync(0xffffffffu, mx1, 2));

        const float mnew0 = fmaxf(mrun0, mx0), mnew1 = fmaxf(mrun1, mx1);
        const float corr0 = __expf(mrun0 - mnew0), corr1 = __expf(mrun1 - mnew1);
        mrun0 = mnew0; mrun1 = mnew1;

        __syncthreads();

        float l0 = 0.f, l1 = 0.f;
#pragma unroll
        for (int ni = 0; ni < 8; ni++) {
            const float p0 = __expf(sacc[ni][0] - mnew0);
            const float p1 = __expf(sacc[ni][1] - mnew0);
            const float p2 = __expf(sacc[ni][2] - mnew1);
            const float p3 = __expf(sacc[ni][3] - mnew1);
            l0 += p0 + p1; l1 += p2 + p3;
            const int c = ni * 8 + (lc << 1);
            Ks[(wm + lr) * KS_ST + c]     = f2tf(p0);
            Ks[(wm + lr) * KS_ST + c + 1] = f2tf(p1);
            Ks[(wm + lr + 8) * KS_ST + c]     = f2tf(p2);
            Ks[(wm + lr + 8) * KS_ST + c + 1] = f2tf(p3);
        }
        l0 += __shfl_xor_sync(0xffffffffu, l0, 1);
        l0 += __shfl_xor_sync(0xffffffffu, l0, 2);
        l1 += __shfl_xor_sync(0xffffffffu, l1, 1);
        l1 += __shfl_xor_sync(0xffffffffu, l1, 2);
        lrun0 = lrun0 * corr0 + l0;
        lrun1 = lrun1 * corr1 + l1;
#pragma unroll
        for (int ni = 0; ni < 8; ni++) {
            oacc[ni][0] *= corr0; oacc[ni][1] *= corr0;
            oacc[ni][2] *= corr1; oacc[ni][3] *= corr1;
        }
        __syncwarp();

#pragma unroll
        for (int kt = 0; kt < 8; kt++) {
            unsigned af[4];
            af[0] = Ks[(wm + lr) * KS_ST + kt * 8 + lc];
            af[1] = Ks[(wm + lr + 8) * KS_ST + kt * 8 + lc];
            af[2] = Ks[(wm + lr) * KS_ST + kt * 8 + 4 + lc];
            af[3] = Ks[(wm + lr + 8) * KS_ST + kt * 8 + 4 + lc];
            unsigned bf[8][2];
#pragma unroll
            for (int ni = 0; ni < 8; ni++) {
                const int col = ni * 8 + lr;
                bf[ni][0] = Vs[(kt * 8 + lc) * VS_ST + col];
                bf[ni][1] = Vs[(kt * 8 + 4 + lc) * VS_ST + col];
            }
#pragma unroll
            for (int ni = 0; ni < 8; ni++) mma_tf32(oacc[ni], af, bf[ni]);
        }
    }

    const float inv0 = 1.f / lrun0, inv1 = 1.f / lrun1;
    const int r0 = m0 + wm + lr;
#pragma unroll
    for (int ni = 0; ni < 8; ni++) {
        const int c = h * 64 + ni * 8 + (lc << 1);
        float2 o0, o1;
        o0.x = __uint_as_float(f2tf(oacc[ni][0] * inv0));
        o0.y = __uint_as_float(f2tf(oacc[ni][1] * inv0));
        o1.x = __uint_as_float(f2tf(oacc[ni][2] * inv1));
        o1.y = __uint_as_float(f2tf(oacc[ni][3] * inv1));
        *(float2*)&g_attno[(size_t)r0 * DD + c] = o0;
        *(float2*)&g_attno[(size_t)(r0 + 8) * DD + c] = o1;
    }
}

// -----------------------------------------------------------------------------
extern "C" void kernel_launch(void* const* d_in, const int* in_sizes, int n_in,
                              void* d_out, int out_size)
{
    const float* x            = (const float*)d_in[0];
    const float* qkv_w        = (const float*)d_in[1];
    const float* qkv_b        = (const float*)d_in[2];
    const float* w1_write     = (const float*)d_in[3];
    const float* w2_write     = (const float*)d_in[4];
    const float* w1_read      = (const float*)d_in[5];
    const float* w2_read      = (const float*)d_in[6];
    const float* kv_geo_w     = (const float*)d_in[7];
    const float* out_w        = (const float*)d_in[8];
    const float* out_b        = (const float*)d_in[9];
    const float* kv_gate      = (const float*)d_in[10];
    const float* mem_scale    = (const float*)d_in[11];
    const float* decay_logits = (const float*)d_in[12];
    float* out = (float*)d_out;

    float *p_qkv, *p_kvgeo, *p_attno, *p_xr, *p_qwr, *p_gwr, *p_owr;
    cudaGetSymbolAddress((void**)&p_qkv,   g_qkv);
    cudaGetSymbolAddress((void**)&p_kvgeo, g_kvgeo);
    cudaGetSymbolAddress((void**)&p_attno, g_attno);
    cudaGetSymbolAddress((void**)&p_xr,    g_xr);
    cudaGetSymbolAddress((void**)&p_qwr,   g_qwr);
    cudaGetSymbolAddress((void**)&p_gwr,   g_gwr);
    cudaGetSymbolAddress((void**)&p_owr,   g_owr);

    cudaFuncSetAttribute(gemm_tf32, cudaFuncAttributeMaxDynamicSharedMemorySize,
                         GEMM_SMEM_BYTES);

    // One-time creation of the side stream + fork/join events.
    static cudaStream_t s1 = nullptr;
    static cudaEvent_t ev_fork = nullptr, ev_x = nullptr, ev_qw = nullptr;
    static cudaEvent_t ev_gw = nullptr, ev_join = nullptr;
    static cudaEvent_t ev_attn = nullptr, ev_tail = nullptr;
    if (s1 == nullptr) {
        cudaStreamCreateWithFlags(&s1, cudaStreamNonBlocking);
        cudaEventCreateWithFlags(&ev_fork, cudaEventDisableTiming);
        cudaEventCreateWithFlags(&ev_x, cudaEventDisableTiming);
        cudaEventCreateWithFlags(&ev_qw, cudaEventDisableTiming);
        cudaEventCreateWithFlags(&ev_gw, cudaEventDisableTiming);
        cudaEventCreateWithFlags(&ev_join, cudaEventDisableTiming);
        cudaEventCreateWithFlags(&ev_attn, cudaEventDisableTiming);
        cudaEventCreateWithFlags(&ev_tail, cudaEventDisableTiming);
    }

    // ---- fork immediately: s1 starts weight rounding in parallel with x ----
    cudaEventRecord(ev_fork, 0);
    cudaStreamWaitEvent(s1, ev_fork, 0);

    // s1: weight roundings (no dependency on x)
    round_tf32<<<(DD * 3 * DD / 4) / 256, 256, 0, s1>>>((const float4*)qkv_w, (float4*)p_qwr);
    cudaEventRecord(ev_qw, s1);
    round_tf32<<<(DD * 2 * DD / 4) / 256, 256, 0, s1>>>((const float4*)kv_geo_w, (float4*)p_gwr);
    cudaEventRecord(ev_gw, s1);
    round_tf32<<<(DD * DD / 4) / 256, 256, 0, s1>>>((const float4*)out_w, (float4*)p_owr);

    // main: round x
    round_tf32<<<(TT * DD / 4) / 256, 256>>>((const float4*)x, (float4*)p_xr);
    cudaEventRecord(ev_x, 0);

    // s1 continues with x-dependent side chain: proj -> lines -> memscore
    cudaStreamWaitEvent(s1, ev_x, 0);
    gemm_proj<<<dim3(1, TT / 128, 4), 256, 0, s1>>>(p_xr, w1_write, w2_write, w1_read, w2_read);
    lines_kernel<<<(TT * HH) / 256, 256, 0, s1>>>();
    memscore<<<dim3(TT, HH), 128, 0, s1>>>(decay_logits, mem_scale);
    cudaEventRecord(ev_join, s1);

    // main: the two big GEMMs (gated on their weight roundings)
    cudaStreamWaitEvent(0, ev_qw, 0);
    gemm_tf32<<<dim3(3072 / 64, TT / 128), 256, GEMM_SMEM_BYTES>>>(p_xr, p_qwr, qkv_b, p_qkv, TT, 3072, DD);
    cudaStreamWaitEvent(0, ev_gw, 0);
    gemm_tf32<<<dim3(2048 / 64, TT / 128), 256, GEMM_SMEM_BYTES>>>(p_xr, p_gwr, nullptr, p_kvgeo, TT, 2048, DD);

    // ---- join: enhance needs gate (s1) + qkv/kvgeo (s0) ----
    cudaStreamWaitEvent(0, ev_join, 0);
    enhance<<<(HH * TT * 16) / 256, 256>>>(kv_gate);

    // ---- fork 2: split attn + out GEMM into low/high halves --------------
    cudaEventRecord(ev_attn, 0);
    cudaStreamWaitEvent(s1, ev_attn, 0);
    // s1: short half (query tiles 0..15) then out rows [0, 1024)
    attn<<<dim3(16, HH), 128, 0, s1>>>(0);
    gemm_tf32<<<dim3(DD / 64, 8), 256, GEMM_SMEM_BYTES, s1>>>(p_attno, p_owr, out_b, out, 1024, DD, DD);
    cudaEventRecord(ev_tail, s1);
    // stream 0: long half (query tiles 16..31) then out rows [1024, 2048)
    attn<<<dim3(16, HH), 128>>>(16);
    gemm_tf32<<<dim3(DD / 64, 8), 256, GEMM_SMEM_BYTES>>>(p_attno + (size_t)1024 * DD, p_owr, out_b, out + (size_t)1024 * DD, 1024, DD, DD);
    cudaStreamWaitEvent(0, ev_tail, 0);
}